// round 7
// baseline (speedup 1.0000x reference)
#include <cuda_runtime.h>
#include <cuda_bf16.h>
#include <math.h>
#include <stdint.h>

// Problem constants
#define BB 2
#define SS 2048
#define DD 2048
#define HH 16
#define DK 128
#define MM (BB*SS)          // 4096
#define KEY_SCALE 0.08838834764831843f  // 1/sqrt(128)

// -------------------- scratch (device globals; no allocations) --------------------
__device__ float g_q[(size_t)BB*HH*SS*DK];   // [b,h,s,dk]
__device__ float g_k[(size_t)BB*HH*SS*DK];
__device__ float g_v[(size_t)BB*HH*SS*DK];
__device__ float g_gate[(size_t)BB*SS*HH];   // [b,s,h]
__device__ float g_o[(size_t)BB*SS*DD];      // [b,s,h*dk]

__device__ __forceinline__ uint32_t tf32u(float x) {
    uint32_t u;
    asm("cvt.rna.tf32.f32 %0, %1;" : "=r"(u) : "f"(x));
    return u;
}
__device__ __forceinline__ float tf32f(float x) { return __uint_as_float(tf32u(x)); }

__device__ __forceinline__ void mma_tf32(float* d, const uint32_t* a, const uint32_t* b) {
    asm volatile(
        "mma.sync.aligned.m16n8k8.row.col.f32.tf32.tf32.f32 "
        "{%0,%1,%2,%3}, {%4,%5,%6,%7}, {%8,%9}, {%0,%1,%2,%3};"
        : "+f"(d[0]), "+f"(d[1]), "+f"(d[2]), "+f"(d[3])
        : "r"(a[0]), "r"(a[1]), "r"(a[2]), "r"(a[3]), "r"(b[0]), "r"(b[1]));
}

// ==================== TF32 tensor-core GEMM (128x256 CTA tile, 64x64 warp tiles) ====
// C[M,N] = X[M,K] * Wz[N,K]^T + bz   (K = DD), weight selected by blockIdx.z
// mode 0: out row-major [M,N];  mode 1: out scattered to [b,h,s,dk]
#define TBM 128
#define TBN 256
#define TBK 16
#define TLD 20
#define KTILES (DD / TBK)
#define A_STG (TBM * TLD)                 // 2560 floats
#define B_STG (TBN * TLD)                 // 5120 floats
#define GEMM_SMEM_BYTES (3 * (A_STG + B_STG) * 4)   // 92160

__global__ __launch_bounds__(256, 1) void gemm_tf32(const float* __restrict__ X,
                                                    const float* __restrict__ W0,
                                                    const float* __restrict__ b0, float* o0,
                                                    const float* __restrict__ W1,
                                                    const float* __restrict__ b1, float* o1,
                                                    const float* __restrict__ W2,
                                                    const float* __restrict__ b2, float* o2,
                                                    int mode) {
    extern __shared__ float gsm[];
    float* Asm = gsm;                       // [3][A_STG]
    float* Bsm = gsm + 3 * A_STG;           // [3][B_STG]

    const int z = blockIdx.z;
    const float* W    = (z == 0) ? W0 : (z == 1) ? W1 : W2;
    const float* bias = (z == 0) ? b0 : (z == 1) ? b1 : b2;
    float* out        = (z == 0) ? o0 : (z == 1) ? o1 : o2;

    const int tid  = threadIdx.x;
    const int lane = tid & 31;
    const int warp = tid >> 5;
    const int gid  = lane >> 2;
    const int ctid = lane & 3;
    const int mw   = (warp >> 2) * 64;      // 0 or 64
    const int nw   = (warp & 3) * 64;       // 0,64,128,192

    const int m0 = blockIdx.y * TBM;
    const int n0 = blockIdx.x * TBN;

    const int lrow = tid >> 2;              // 0..63
    const int lcol = (tid & 3) * 4;         // 0,4,8,12

    const float* Xp0 = X + (size_t)(m0 + lrow) * DD + lcol;
    const float* Xp1 = X + (size_t)(m0 + lrow + 64) * DD + lcol;
    const float* Wp0 = W + (size_t)(n0 + lrow) * DD + lcol;
    const float* Wp1 = W + (size_t)(n0 + lrow + 64) * DD + lcol;
    const float* Wp2 = W + (size_t)(n0 + lrow + 128) * DD + lcol;
    const float* Wp3 = W + (size_t)(n0 + lrow + 192) * DD + lcol;

    float4 sx0, sx1, sw0, sw1, sw2, sw3;

#define LDG_TILE(t) do {                                        \
        const size_t off = (size_t)(t) * TBK;                   \
        sx0 = *(const float4*)(Xp0 + off);                      \
        sx1 = *(const float4*)(Xp1 + off);                      \
        sw0 = *(const float4*)(Wp0 + off);                      \
        sw1 = *(const float4*)(Wp1 + off);                      \
        sw2 = *(const float4*)(Wp2 + off);                      \
        sw3 = *(const float4*)(Wp3 + off);                      \
    } while (0)

#define ST4(p, v) do { (p)[0] = tf32f((v).x); (p)[1] = tf32f((v).y);   \
                       (p)[2] = tf32f((v).z); (p)[3] = tf32f((v).w); } while (0)

#define STS_TILE(buf) do {                                              \
        float* ab = Asm + (buf) * A_STG;                                \
        float* bb = Bsm + (buf) * B_STG;                                \
        ST4(&ab[(lrow)       * TLD + lcol], sx0);                       \
        ST4(&ab[(lrow + 64)  * TLD + lcol], sx1);                       \
        ST4(&bb[(lrow)       * TLD + lcol], sw0);                       \
        ST4(&bb[(lrow + 64)  * TLD + lcol], sw1);                       \
        ST4(&bb[(lrow + 128) * TLD + lcol], sw2);                       \
        ST4(&bb[(lrow + 192) * TLD + lcol], sw3);                       \
    } while (0)

    float acc[4][8][4];
#pragma unroll
    for (int i = 0; i < 4; ++i)
#pragma unroll
        for (int j = 0; j < 8; ++j)
#pragma unroll
            for (int r = 0; r < 4; ++r) acc[i][j][r] = 0.f;

    LDG_TILE(0);
    STS_TILE(0);
    LDG_TILE(1);

    for (int t = 0; t < KTILES; ++t) {
        const int bufc = t % 3;
        if (t + 1 < KTILES) STS_TILE((t + 1) % 3);
        if (t + 2 < KTILES) LDG_TILE(t + 2);
        __syncthreads();

        const float* Ab = Asm + bufc * A_STG;
        const float* Bb = Bsm + bufc * B_STG;

#pragma unroll
        for (int ks = 0; ks < 2; ++ks) {
            const int kk = ks * 8;
            uint32_t a[4][4], b[8][2];
#pragma unroll
            for (int mt = 0; mt < 4; ++mt) {
                const int r = mw + mt * 16 + gid;
                a[mt][0] = __float_as_uint(Ab[(r)     * TLD + kk + ctid]);
                a[mt][1] = __float_as_uint(Ab[(r + 8) * TLD + kk + ctid]);
                a[mt][2] = __float_as_uint(Ab[(r)     * TLD + kk + ctid + 4]);
                a[mt][3] = __float_as_uint(Ab[(r + 8) * TLD + kk + ctid + 4]);
            }
#pragma unroll
            for (int nt = 0; nt < 8; ++nt) {
                const int c = nw + nt * 8 + gid;
                b[nt][0] = __float_as_uint(Bb[c * TLD + kk + ctid]);
                b[nt][1] = __float_as_uint(Bb[c * TLD + kk + ctid + 4]);
            }
#pragma unroll
            for (int mt = 0; mt < 4; ++mt)
#pragma unroll
                for (int nt = 0; nt < 8; ++nt)
                    mma_tf32(acc[mt][nt], a[mt], b[nt]);
        }
    }

    // epilogue
#pragma unroll
    for (int mt = 0; mt < 4; ++mt) {
#pragma unroll
        for (int nt = 0; nt < 8; ++nt) {
            const int row0 = m0 + mw + mt * 16 + gid;
            const int col  = n0 + nw + nt * 8 + ctid * 2;
            const float c0 = bias[col], c1 = bias[col + 1];
            float2 v0 = make_float2(acc[mt][nt][0] + c0, acc[mt][nt][1] + c1);
            float2 v1 = make_float2(acc[mt][nt][2] + c0, acc[mt][nt][3] + c1);
            if (mode == 0) {
                *(float2*)&out[(size_t)row0 * DD + col] = v0;
                *(float2*)&out[(size_t)(row0 + 8) * DD + col] = v1;
            } else {
                const int h_ = col >> 7, dk_ = col & (DK - 1);
                const int b0_ = row0 >> 11, s0_ = row0 & (SS - 1);
                const int s1_ = (row0 + 8) & (SS - 1);
                *(float2*)&out[(((size_t)(b0_ * HH + h_) * SS) + s0_) * DK + dk_] = v0;
                *(float2*)&out[(((size_t)(b0_ * HH + h_) * SS) + s1_) * DK + dk_] = v1;
            }
        }
    }
#undef LDG_TILE
#undef ST4
#undef STS_TILE
}

// ==================== gate ====================
__global__ __launch_bounds__(128) void gate_kernel(const float* __restrict__ X,
                                                   const float* __restrict__ Wg,
                                                   const float* __restrict__ bg,
                                                   float* __restrict__ gate) {
    __shared__ float xs[DD];
    const int m = blockIdx.x;
    for (int i = threadIdx.x * 4; i < DD; i += 128 * 4)
        *(float4*)&xs[i] = *(const float4*)&X[(size_t)m * DD + i];
    __syncthreads();

    const int w = threadIdx.x >> 5, lane = threadIdx.x & 31;
    for (int h = w; h < HH; h += 4) {
        const float* wg = &Wg[(size_t)h * DD];
        float sum = 0.f;
        for (int k = lane; k < DD; k += 32) sum += xs[k] * wg[k];
#pragma unroll
        for (int off = 16; off; off >>= 1) sum += __shfl_xor_sync(0xffffffffu, sum, off);
        if (lane == 0) {
            const float zv = sum + bg[h];
            gate[(size_t)m * HH + h] = 1.f / (1.f + __expf(-zv));
        }
    }
}

// ==================== flash attention (tf32 warp mma) ====================
#define AQ 128
#define AK 64
#define KS_LD 132
#define VT_LD 68
#define ATTN_SMEM_BYTES ((AK * KS_LD + DK * VT_LD) * 4)

__global__ __launch_bounds__(256, 1) void attn_mma(const float* __restrict__ q,
                                                   const float* __restrict__ k,
                                                   const float* __restrict__ v,
                                                   const float* __restrict__ gate,
                                                   float* __restrict__ o,
                                                   const float* __restrict__ head_scale) {
    extern __shared__ float sm[];
    float* Ks = sm;
    float* Vt = sm + AK * KS_LD;

    const int qb   = gridDim.x - 1 - blockIdx.x;
    const int h    = blockIdx.y;
    const int b    = blockIdx.z;
    const int tid  = threadIdx.x;
    const int lane = tid & 31;
    const int warp = tid >> 5;
    const int gid  = lane >> 2;
    const int ctid = lane & 3;
    const float hs = head_scale[h];
    const size_t bh = ((size_t)b * HH + h) * SS;

    const int rowA = qb * AQ + warp * 16 + gid;
    const int rowB = rowA + 8;

    uint32_t qa[16][4];
    {
        const float* qA = q + (bh + rowA) * DK;
        const float* qB = q + (bh + rowB) * DK;
#pragma unroll
        for (int kc = 0; kc < 16; ++kc) {
            qa[kc][0] = tf32u(qA[8 * kc + ctid]);
            qa[kc][1] = tf32u(qB[8 * kc + ctid]);
            qa[kc][2] = tf32u(qA[8 * kc + ctid + 4]);
            qa[kc][3] = tf32u(qB[8 * kc + ctid + 4]);
        }
    }

    float oacc[16][4];
#pragma unroll
    for (int nt = 0; nt < 16; ++nt)
#pragma unroll
        for (int r = 0; r < 4; ++r) oacc[nt][r] = 0.f;

    float mA = -INFINITY, mB = -INFINITY, lA = 0.f, lB = 0.f;

    const int ktmax = 2 * qb + 1;
    for (int kt = 0; kt <= ktmax; ++kt) {
        __syncthreads();

        {
            int s = tid;
#pragma unroll
            for (int i = 0; i < 8; ++i, s += 256) {
                const int r = s >> 5, c4 = (s & 31) * 4;
                float4 xv = *(const float4*)&k[(bh + (size_t)kt * AK + r) * DK + c4];
                *(float4*)&Ks[r * KS_LD + c4] =
                    make_float4(tf32f(xv.x), tf32f(xv.y), tf32f(xv.z), tf32f(xv.w));
            }
        }
        {
#pragma unroll
            for (int i = 0; i < 8; ++i) {
                const int r = i * 8 + (lane >> 2);
                const int c = warp * 16 + (lane & 3) * 4;
                float4 xv = *(const float4*)&v[(bh + (size_t)kt * AK + r) * DK + c];
                Vt[(c + 0) * VT_LD + r] = tf32f(xv.x);
                Vt[(c + 1) * VT_LD + r] = tf32f(xv.y);
                Vt[(c + 2) * VT_LD + r] = tf32f(xv.z);
                Vt[(c + 3) * VT_LD + r] = tf32f(xv.w);
            }
        }
        __syncthreads();

        float sacc[8][4];
#pragma unroll
        for (int nt = 0; nt < 8; ++nt)
#pragma unroll
            for (int r = 0; r < 4; ++r) sacc[nt][r] = 0.f;

#pragma unroll
        for (int kc = 0; kc < 16; ++kc) {
#pragma unroll
            for (int nt = 0; nt < 8; ++nt) {
                uint32_t bfr[2];
                const float* kp = &Ks[(8 * nt + gid) * KS_LD + 8 * kc + ctid];
                bfr[0] = __float_as_uint(kp[0]);
                bfr[1] = __float_as_uint(kp[4]);
                mma_tf32(sacc[nt], qa[kc], bfr);
            }
        }

        const int kbase = kt * AK;
#pragma unroll
        for (int nt = 0; nt < 8; ++nt) {
            const int c0 = kbase + 8 * nt + 2 * ctid;
            const int c1 = c0 + 1;
            sacc[nt][0] = (c0 <= rowA) ? sacc[nt][0] * KEY_SCALE + (float)(c0 - rowA) * hs : -INFINITY;
            sacc[nt][1] = (c1 <= rowA) ? sacc[nt][1] * KEY_SCALE + (float)(c1 - rowA) * hs : -INFINITY;
            sacc[nt][2] = (c0 <= rowB) ? sacc[nt][2] * KEY_SCALE + (float)(c0 - rowB) * hs : -INFINITY;
            sacc[nt][3] = (c1 <= rowB) ? sacc[nt][3] * KEY_SCALE + (float)(c1 - rowB) * hs : -INFINITY;
        }

        float mxA = -INFINITY, mxB = -INFINITY;
#pragma unroll
        for (int nt = 0; nt < 8; ++nt) {
            mxA = fmaxf(mxA, fmaxf(sacc[nt][0], sacc[nt][1]));
            mxB = fmaxf(mxB, fmaxf(sacc[nt][2], sacc[nt][3]));
        }
        mxA = fmaxf(mxA, __shfl_xor_sync(0xffffffffu, mxA, 1));
        mxA = fmaxf(mxA, __shfl_xor_sync(0xffffffffu, mxA, 2));
        mxB = fmaxf(mxB, __shfl_xor_sync(0xffffffffu, mxB, 1));
        mxB = fmaxf(mxB, __shfl_xor_sync(0xffffffffu, mxB, 2));

        const float mA_new = fmaxf(mA, mxA);
        const float mB_new = fmaxf(mB, mxB);
        const float alphaA = __expf(mA - mA_new);
        const float alphaB = __expf(mB - mB_new);
        mA = mA_new; mB = mB_new;

        float rsA = 0.f, rsB = 0.f;
        uint32_t pfrag[8][4];
        const int qsrc0 = (lane & ~3) + (ctid >> 1);
        const int qsrc2 = qsrc0 + 2;
        const bool oddc = (ctid & 1);
#pragma unroll
        for (int nt = 0; nt < 8; ++nt) {
            float p0 = __expf(sacc[nt][0] - mA_new);
            float p1 = __expf(sacc[nt][1] - mA_new);
            float p2 = __expf(sacc[nt][2] - mB_new);
            float p3 = __expf(sacc[nt][3] - mB_new);
            rsA += p0 + p1;
            rsB += p2 + p3;
            uint32_t t0 = tf32u(p0), t1 = tf32u(p1), t2 = tf32u(p2), t3 = tf32u(p3);
            uint32_t v00 = __shfl_sync(0xffffffffu, t0, qsrc0);
            uint32_t v01 = __shfl_sync(0xffffffffu, t1, qsrc0);
            uint32_t v20 = __shfl_sync(0xffffffffu, t0, qsrc2);
            uint32_t v21 = __shfl_sync(0xffffffffu, t1, qsrc2);
            uint32_t w00 = __shfl_sync(0xffffffffu, t2, qsrc0);
            uint32_t w01 = __shfl_sync(0xffffffffu, t3, qsrc0);
            uint32_t w20 = __shfl_sync(0xffffffffu, t2, qsrc2);
            uint32_t w21 = __shfl_sync(0xffffffffu, t3, qsrc2);
            pfrag[nt][0] = oddc ? v01 : v00;
            pfrag[nt][1] = oddc ? w01 : w00;
            pfrag[nt][2] = oddc ? v21 : v20;
            pfrag[nt][3] = oddc ? w21 : w20;
        }
        rsA += __shfl_xor_sync(0xffffffffu, rsA, 1);
        rsA += __shfl_xor_sync(0xffffffffu, rsA, 2);
        rsB += __shfl_xor_sync(0xffffffffu, rsB, 1);
        rsB += __shfl_xor_sync(0xffffffffu, rsB, 2);
        lA = lA * alphaA + rsA;
        lB = lB * alphaB + rsB;

#pragma unroll
        for (int nt = 0; nt < 16; ++nt) {
            oacc[nt][0] *= alphaA; oacc[nt][1] *= alphaA;
            oacc[nt][2] *= alphaB; oacc[nt][3] *= alphaB;
        }
#pragma unroll
        for (int kc = 0; kc < 8; ++kc) {
#pragma unroll
            for (int nt = 0; nt < 16; ++nt) {
                uint32_t bfr[2];
                const float* vp = &Vt[(8 * nt + gid) * VT_LD + 8 * kc + ctid];
                bfr[0] = __float_as_uint(vp[0]);
                bfr[1] = __float_as_uint(vp[4]);
                mma_tf32(oacc[nt], pfrag[kc], bfr);
            }
        }
    }

    const float gA = gate[((size_t)b * SS + rowA) * HH + h] / lA;
    const float gB = gate[((size_t)b * SS + rowB) * HH + h] / lB;
#pragma unroll
    for (int nt = 0; nt < 16; ++nt) {
        const int col = h * DK + 8 * nt + 2 * ctid;
        float2 vA = make_float2(oacc[nt][0] * gA, oacc[nt][1] * gA);
        float2 vB = make_float2(oacc[nt][2] * gB, oacc[nt][3] * gB);
        *(float2*)&o[((size_t)b * SS + rowA) * DD + col] = vA;
        *(float2*)&o[((size_t)b * SS + rowB) * DD + col] = vB;
    }
}

// ==================== launcher ====================
extern "C" void kernel_launch(void* const* d_in, const int* in_sizes, int n_in,
                              void* d_out, int out_size) {
    const float* states     = (const float*)d_in[0];
    const float* head_scale = (const float*)d_in[2];
    const float* Wq = (const float*)d_in[3];
    const float* bq = (const float*)d_in[4];
    const float* Wk = (const float*)d_in[5];
    const float* bk = (const float*)d_in[6];
    const float* Wv = (const float*)d_in[7];
    const float* bv = (const float*)d_in[8];
    const float* Wg = (const float*)d_in[9];
    const float* bg = (const float*)d_in[10];
    const float* Wo = (const float*)d_in[11];
    const float* bo = (const float*)d_in[12];

    float *qb_, *kb_, *vb_, *gb_, *ob_;
    cudaGetSymbolAddress((void**)&qb_, g_q);
    cudaGetSymbolAddress((void**)&kb_, g_k);
    cudaGetSymbolAddress((void**)&vb_, g_v);
    cudaGetSymbolAddress((void**)&gb_, g_gate);
    cudaGetSymbolAddress((void**)&ob_, g_o);

    cudaFuncSetAttribute(attn_mma, cudaFuncAttributeMaxDynamicSharedMemorySize,
                         ATTN_SMEM_BYTES);
    cudaFuncSetAttribute(gemm_tf32, cudaFuncAttributeMaxDynamicSharedMemorySize,
                         GEMM_SMEM_BYTES);

    // fused QKV projection: blockIdx.z selects weight/bias/output
    dim3 qkv_grid(DD / TBN, MM / TBM, 3);   // (8, 32, 3)
    gemm_tf32<<<qkv_grid, 256, GEMM_SMEM_BYTES>>>(states,
        Wq, bq, qb_, Wk, bk, kb_, Wv, bv, vb_, 1);

    gate_kernel<<<MM, 128>>>(states, Wg, bg, gb_);

    dim3 attn_grid(SS / AQ, HH, BB);        // (16, 16, 2)
    attn_mma<<<attn_grid, 256, ATTN_SMEM_BYTES>>>(qb_, kb_, vb_, gb_, ob_, head_scale);

    dim3 out_grid(DD / TBN, MM / TBM, 1);   // (8, 32, 1)
    gemm_tf32<<<out_grid, 256, GEMM_SMEM_BYTES>>>(ob_,
        Wo, bo, (float*)d_out, Wo, bo, (float*)d_out, Wo, bo, (float*)d_out, 0);
}

// round 8
// speedup vs baseline: 1.1608x; 1.1608x over previous
#include <cuda_runtime.h>
#include <cuda_bf16.h>
#include <math.h>
#include <stdint.h>

// Problem constants
#define BB 2
#define SS 2048
#define DD 2048
#define HH 16
#define DK 128
#define MM (BB*SS)          // 4096
#define KEY_SCALE 0.08838834764831843f  // 1/sqrt(128)

// -------------------- scratch (device globals; no allocations) --------------------
__device__ float g_q[(size_t)BB*HH*SS*DK];   // [b,h,s,dk]
__device__ float g_k[(size_t)BB*HH*SS*DK];
__device__ float g_v[(size_t)BB*HH*SS*DK];
__device__ float g_gate[(size_t)BB*SS*HH];   // [b,s,h]
__device__ float g_o[(size_t)BB*SS*DD];      // [b,s,h*dk] (tf32-rounded by attn)
__device__ float g_xr[(size_t)MM*DD];        // states tf32-rounded
__device__ float g_wq[(size_t)DD*DD];
__device__ float g_wk[(size_t)DD*DD];
__device__ float g_wv[(size_t)DD*DD];
__device__ float g_wo[(size_t)DD*DD];

__device__ __forceinline__ uint32_t tf32u(float x) {
    uint32_t u;
    asm("cvt.rna.tf32.f32 %0, %1;" : "=r"(u) : "f"(x));
    return u;
}
__device__ __forceinline__ float tf32f(float x) { return __uint_as_float(tf32u(x)); }

__device__ __forceinline__ void mma_tf32(float* d, const uint32_t* a, const uint32_t* b) {
    asm volatile(
        "mma.sync.aligned.m16n8k8.row.col.f32.tf32.tf32.f32 "
        "{%0,%1,%2,%3}, {%4,%5,%6,%7}, {%8,%9}, {%0,%1,%2,%3};"
        : "+f"(d[0]), "+f"(d[1]), "+f"(d[2]), "+f"(d[3])
        : "r"(a[0]), "r"(a[1]), "r"(a[2]), "r"(a[3]), "r"(b[0]), "r"(b[1]));
}

static __device__ __forceinline__ void cp_async16(uint32_t dst, const void* src) {
    asm volatile("cp.async.cg.shared.global [%0], [%1], 16;" :: "r"(dst), "l"(src));
}
static __device__ __forceinline__ void cp_commit_group() {
    asm volatile("cp.async.commit_group;");
}
template <int N>
static __device__ __forceinline__ void cp_wait_group() {
    asm volatile("cp.async.wait_group %0;" :: "n"(N));
}

// ==================== tf32 pre-rounding ====================
__global__ __launch_bounds__(256) void round_tf32_kernel(const float* __restrict__ in,
                                                         float* __restrict__ out, int n4) {
    const int i = blockIdx.x * 256 + threadIdx.x;
    if (i < n4) {
        float4 v = ((const float4*)in)[i];
        ((float4*)out)[i] = make_float4(tf32f(v.x), tf32f(v.y), tf32f(v.z), tf32f(v.w));
    }
}

// ==================== TF32 GEMM: cp.async 4-stage, 128x256 CTA, 64x64 warp tiles ====
// C[M,N] = X[M,K] * Wz[N,K]^T + bz  (K = DD).  Inputs pre-rounded tf32.
// mode 0: out row-major [M,N];  mode 1: scattered [b,h,s,dk]
#define TBM 128
#define TBN 256
#define TBK 32
#define TLD 36                               // floats per row (32 + 4 pad), 144B
#define KT (DD / TBK)                        // 64
#define A_STG (TBM * TLD)                    // 4608 floats
#define B_STG (TBN * TLD)                    // 9216 floats
#define NST 4
#define STG_FL (A_STG + B_STG)               // 13824 floats per stage
#define GEMM_SMEM_BYTES (NST * STG_FL * 4)   // 221184

__global__ __launch_bounds__(256, 1) void gemm_tf32(const float* __restrict__ X,
                                                    const float* __restrict__ W0,
                                                    const float* __restrict__ b0, float* o0,
                                                    const float* __restrict__ W1,
                                                    const float* __restrict__ b1, float* o1,
                                                    const float* __restrict__ W2,
                                                    const float* __restrict__ b2, float* o2,
                                                    int mode) {
    extern __shared__ float gsm[];

    const int z = blockIdx.z;
    const float* W    = (z == 0) ? W0 : (z == 1) ? W1 : W2;
    const float* bias = (z == 0) ? b0 : (z == 1) ? b1 : b2;
    float* out        = (z == 0) ? o0 : (z == 1) ? o1 : o2;

    const int tid  = threadIdx.x;
    const int lane = tid & 31;
    const int warp = tid >> 5;
    const int gid  = lane >> 2;
    const int ctid = lane & 3;
    const int mw   = (warp >> 2) * 64;       // 0 or 64
    const int nw   = (warp & 3) * 64;        // 0,64,128,192

    const int m0 = blockIdx.y * TBM;
    const int n0 = blockIdx.x * TBN;

    const uint32_t sbase = (uint32_t)__cvta_generic_to_shared(gsm);

    // loader mapping: granule g -> row g>>3, 16B-chunk g&7
    const int lr = tid >> 3;                 // base row group helper
    (void)lr;

#define ISSUE(t) do {                                                          \
        const int s_ = (t) % NST;                                              \
        const uint32_t ab = sbase + s_ * (STG_FL * 4);                         \
        const uint32_t bb = ab + A_STG * 4;                                    \
        _Pragma("unroll")                                                      \
        for (int i_ = 0; i_ < 4; ++i_) {                                       \
            const int g_ = i_ * 256 + tid;                                     \
            const int r_ = g_ >> 3, c_ = g_ & 7;                               \
            cp_async16(ab + r_ * 144 + c_ * 16,                                \
                       X + (size_t)(m0 + r_) * DD + (t) * TBK + c_ * 4);       \
        }                                                                      \
        _Pragma("unroll")                                                      \
        for (int i_ = 0; i_ < 8; ++i_) {                                       \
            const int g_ = i_ * 256 + tid;                                     \
            const int r_ = g_ >> 3, c_ = g_ & 7;                               \
            cp_async16(bb + r_ * 144 + c_ * 16,                                \
                       W + (size_t)(n0 + r_) * DD + (t) * TBK + c_ * 4);       \
        }                                                                      \
        cp_commit_group();                                                     \
    } while (0)

    float acc[4][8][4];
#pragma unroll
    for (int i = 0; i < 4; ++i)
#pragma unroll
        for (int j = 0; j < 8; ++j)
#pragma unroll
            for (int r = 0; r < 4; ++r) acc[i][j][r] = 0.f;

    // prologue: fill 3 of 4 stages
    ISSUE(0);
    ISSUE(1);
    ISSUE(2);

    for (int t = 0; t < KT; ++t) {
        if (t <= KT - 3)      cp_wait_group<2>();
        else if (t == KT - 2) cp_wait_group<1>();
        else                  cp_wait_group<0>();
        __syncthreads();

        // prefetch t+3 into stage (t+3)%4 == (t-1)%4 (consumed before this barrier)
        if (t + 3 < KT) ISSUE(t + 3);

        const float* Ab = gsm + (t % NST) * STG_FL;
        const float* Bb = Ab + A_STG;

#pragma unroll
        for (int ks = 0; ks < 4; ++ks) {
            const int kk = ks * 8;
            uint32_t a[4][4], b[8][2];
#pragma unroll
            for (int mt = 0; mt < 4; ++mt) {
                const int r = mw + mt * 16 + gid;
                a[mt][0] = __float_as_uint(Ab[(r)     * TLD + kk + ctid]);
                a[mt][1] = __float_as_uint(Ab[(r + 8) * TLD + kk + ctid]);
                a[mt][2] = __float_as_uint(Ab[(r)     * TLD + kk + ctid + 4]);
                a[mt][3] = __float_as_uint(Ab[(r + 8) * TLD + kk + ctid + 4]);
            }
#pragma unroll
            for (int nt = 0; nt < 8; ++nt) {
                const int c = nw + nt * 8 + gid;
                b[nt][0] = __float_as_uint(Bb[c * TLD + kk + ctid]);
                b[nt][1] = __float_as_uint(Bb[c * TLD + kk + ctid + 4]);
            }
#pragma unroll
            for (int mt = 0; mt < 4; ++mt)
#pragma unroll
                for (int nt = 0; nt < 8; ++nt)
                    mma_tf32(acc[mt][nt], a[mt], b[nt]);
        }
    }

    // epilogue
#pragma unroll
    for (int mt = 0; mt < 4; ++mt) {
#pragma unroll
        for (int nt = 0; nt < 8; ++nt) {
            const int row0 = m0 + mw + mt * 16 + gid;
            const int col  = n0 + nw + nt * 8 + ctid * 2;
            const float c0 = bias[col], c1 = bias[col + 1];
            float2 v0 = make_float2(acc[mt][nt][0] + c0, acc[mt][nt][1] + c1);
            float2 v1 = make_float2(acc[mt][nt][2] + c0, acc[mt][nt][3] + c1);
            if (mode == 0) {
                *(float2*)&out[(size_t)row0 * DD + col] = v0;
                *(float2*)&out[(size_t)(row0 + 8) * DD + col] = v1;
            } else {
                const int h_ = col >> 7, dk_ = col & (DK - 1);
                const int b0_ = row0 >> 11, s0_ = row0 & (SS - 1);
                const int s1_ = (row0 + 8) & (SS - 1);
                *(float2*)&out[(((size_t)(b0_ * HH + h_) * SS) + s0_) * DK + dk_] = v0;
                *(float2*)&out[(((size_t)(b0_ * HH + h_) * SS) + s1_) * DK + dk_] = v1;
            }
        }
    }
#undef ISSUE
}

// ==================== gate ====================
__global__ __launch_bounds__(128) void gate_kernel(const float* __restrict__ X,
                                                   const float* __restrict__ Wg,
                                                   const float* __restrict__ bg,
                                                   float* __restrict__ gate) {
    __shared__ float xs[DD];
    const int m = blockIdx.x;
    for (int i = threadIdx.x * 4; i < DD; i += 128 * 4)
        *(float4*)&xs[i] = *(const float4*)&X[(size_t)m * DD + i];
    __syncthreads();

    const int w = threadIdx.x >> 5, lane = threadIdx.x & 31;
    for (int h = w; h < HH; h += 4) {
        const float* wg = &Wg[(size_t)h * DD];
        float sum = 0.f;
        for (int k = lane; k < DD; k += 32) sum += xs[k] * wg[k];
#pragma unroll
        for (int off = 16; off; off >>= 1) sum += __shfl_xor_sync(0xffffffffu, sum, off);
        if (lane == 0) {
            const float zv = sum + bg[h];
            gate[(size_t)m * HH + h] = 1.f / (1.f + __expf(-zv));
        }
    }
}

// ==================== flash attention (tf32 warp mma) ====================
#define AQ 128
#define AK 64
#define KS_LD 132
#define VT_LD 68
#define ATTN_SMEM_BYTES ((AK * KS_LD + DK * VT_LD) * 4)

__global__ __launch_bounds__(256, 1) void attn_mma(const float* __restrict__ q,
                                                   const float* __restrict__ k,
                                                   const float* __restrict__ v,
                                                   const float* __restrict__ gate,
                                                   float* __restrict__ o,
                                                   const float* __restrict__ head_scale) {
    extern __shared__ float sm[];
    float* Ks = sm;
    float* Vt = sm + AK * KS_LD;

    const int qb   = gridDim.x - 1 - blockIdx.x;
    const int h    = blockIdx.y;
    const int b    = blockIdx.z;
    const int tid  = threadIdx.x;
    const int lane = tid & 31;
    const int warp = tid >> 5;
    const int gid  = lane >> 2;
    const int ctid = lane & 3;
    const float hs = head_scale[h];
    const size_t bh = ((size_t)b * HH + h) * SS;

    const int rowA = qb * AQ + warp * 16 + gid;
    const int rowB = rowA + 8;

    uint32_t qa[16][4];
    {
        const float* qA = q + (bh + rowA) * DK;
        const float* qB = q + (bh + rowB) * DK;
#pragma unroll
        for (int kc = 0; kc < 16; ++kc) {
            qa[kc][0] = tf32u(qA[8 * kc + ctid]);
            qa[kc][1] = tf32u(qB[8 * kc + ctid]);
            qa[kc][2] = tf32u(qA[8 * kc + ctid + 4]);
            qa[kc][3] = tf32u(qB[8 * kc + ctid + 4]);
        }
    }

    float oacc[16][4];
#pragma unroll
    for (int nt = 0; nt < 16; ++nt)
#pragma unroll
        for (int r = 0; r < 4; ++r) oacc[nt][r] = 0.f;

    float mA = -INFINITY, mB = -INFINITY, lA = 0.f, lB = 0.f;

    const int ktmax = 2 * qb + 1;
    for (int kt = 0; kt <= ktmax; ++kt) {
        __syncthreads();

        {
            int s = tid;
#pragma unroll
            for (int i = 0; i < 8; ++i, s += 256) {
                const int r = s >> 5, c4 = (s & 31) * 4;
                float4 xv = *(const float4*)&k[(bh + (size_t)kt * AK + r) * DK + c4];
                *(float4*)&Ks[r * KS_LD + c4] =
                    make_float4(tf32f(xv.x), tf32f(xv.y), tf32f(xv.z), tf32f(xv.w));
            }
        }
        {
#pragma unroll
            for (int i = 0; i < 8; ++i) {
                const int r = i * 8 + (lane >> 2);
                const int c = warp * 16 + (lane & 3) * 4;
                float4 xv = *(const float4*)&v[(bh + (size_t)kt * AK + r) * DK + c];
                Vt[(c + 0) * VT_LD + r] = tf32f(xv.x);
                Vt[(c + 1) * VT_LD + r] = tf32f(xv.y);
                Vt[(c + 2) * VT_LD + r] = tf32f(xv.z);
                Vt[(c + 3) * VT_LD + r] = tf32f(xv.w);
            }
        }
        __syncthreads();

        float sacc[8][4];
#pragma unroll
        for (int nt = 0; nt < 8; ++nt)
#pragma unroll
            for (int r = 0; r < 4; ++r) sacc[nt][r] = 0.f;

#pragma unroll
        for (int kc = 0; kc < 16; ++kc) {
#pragma unroll
            for (int nt = 0; nt < 8; ++nt) {
                uint32_t bfr[2];
                const float* kp = &Ks[(8 * nt + gid) * KS_LD + 8 * kc + ctid];
                bfr[0] = __float_as_uint(kp[0]);
                bfr[1] = __float_as_uint(kp[4]);
                mma_tf32(sacc[nt], qa[kc], bfr);
            }
        }

        const int kbase = kt * AK;
#pragma unroll
        for (int nt = 0; nt < 8; ++nt) {
            const int c0 = kbase + 8 * nt + 2 * ctid;
            const int c1 = c0 + 1;
            sacc[nt][0] = (c0 <= rowA) ? sacc[nt][0] * KEY_SCALE + (float)(c0 - rowA) * hs : -INFINITY;
            sacc[nt][1] = (c1 <= rowA) ? sacc[nt][1] * KEY_SCALE + (float)(c1 - rowA) * hs : -INFINITY;
            sacc[nt][2] = (c0 <= rowB) ? sacc[nt][2] * KEY_SCALE + (float)(c0 - rowB) * hs : -INFINITY;
            sacc[nt][3] = (c1 <= rowB) ? sacc[nt][3] * KEY_SCALE + (float)(c1 - rowB) * hs : -INFINITY;
        }

        float mxA = -INFINITY, mxB = -INFINITY;
#pragma unroll
        for (int nt = 0; nt < 8; ++nt) {
            mxA = fmaxf(mxA, fmaxf(sacc[nt][0], sacc[nt][1]));
            mxB = fmaxf(mxB, fmaxf(sacc[nt][2], sacc[nt][3]));
        }
        mxA = fmaxf(mxA, __shfl_xor_sync(0xffffffffu, mxA, 1));
        mxA = fmaxf(mxA, __shfl_xor_sync(0xffffffffu, mxA, 2));
        mxB = fmaxf(mxB, __shfl_xor_sync(0xffffffffu, mxB, 1));
        mxB = fmaxf(mxB, __shfl_xor_sync(0xffffffffu, mxB, 2));

        const float mA_new = fmaxf(mA, mxA);
        const float mB_new = fmaxf(mB, mxB);
        const float alphaA = __expf(mA - mA_new);
        const float alphaB = __expf(mB - mB_new);
        mA = mA_new; mB = mB_new;

        float rsA = 0.f, rsB = 0.f;
        uint32_t pfrag[8][4];
        const int qsrc0 = (lane & ~3) + (ctid >> 1);
        const int qsrc2 = qsrc0 + 2;
        const bool oddc = (ctid & 1);
#pragma unroll
        for (int nt = 0; nt < 8; ++nt) {
            float p0 = __expf(sacc[nt][0] - mA_new);
            float p1 = __expf(sacc[nt][1] - mA_new);
            float p2 = __expf(sacc[nt][2] - mB_new);
            float p3 = __expf(sacc[nt][3] - mB_new);
            rsA += p0 + p1;
            rsB += p2 + p3;
            uint32_t t0 = tf32u(p0), t1 = tf32u(p1), t2 = tf32u(p2), t3 = tf32u(p3);
            uint32_t v00 = __shfl_sync(0xffffffffu, t0, qsrc0);
            uint32_t v01 = __shfl_sync(0xffffffffu, t1, qsrc0);
            uint32_t v20 = __shfl_sync(0xffffffffu, t0, qsrc2);
            uint32_t v21 = __shfl_sync(0xffffffffu, t1, qsrc2);
            uint32_t w00 = __shfl_sync(0xffffffffu, t2, qsrc0);
            uint32_t w01 = __shfl_sync(0xffffffffu, t3, qsrc0);
            uint32_t w20 = __shfl_sync(0xffffffffu, t2, qsrc2);
            uint32_t w21 = __shfl_sync(0xffffffffu, t3, qsrc2);
            pfrag[nt][0] = oddc ? v01 : v00;
            pfrag[nt][1] = oddc ? w01 : w00;
            pfrag[nt][2] = oddc ? v21 : v20;
            pfrag[nt][3] = oddc ? w21 : w20;
        }
        rsA += __shfl_xor_sync(0xffffffffu, rsA, 1);
        rsA += __shfl_xor_sync(0xffffffffu, rsA, 2);
        rsB += __shfl_xor_sync(0xffffffffu, rsB, 1);
        rsB += __shfl_xor_sync(0xffffffffu, rsB, 2);
        lA = lA * alphaA + rsA;
        lB = lB * alphaB + rsB;

#pragma unroll
        for (int nt = 0; nt < 16; ++nt) {
            oacc[nt][0] *= alphaA; oacc[nt][1] *= alphaA;
            oacc[nt][2] *= alphaB; oacc[nt][3] *= alphaB;
        }
#pragma unroll
        for (int kc = 0; kc < 8; ++kc) {
#pragma unroll
            for (int nt = 0; nt < 16; ++nt) {
                uint32_t bfr[2];
                const float* vp = &Vt[(8 * nt + gid) * VT_LD + 8 * kc + ctid];
                bfr[0] = __float_as_uint(vp[0]);
                bfr[1] = __float_as_uint(vp[4]);
                mma_tf32(oacc[nt], pfrag[kc], bfr);
            }
        }
    }

    // epilogue: normalize, gate, tf32-round (out-GEMM consumes via cp.async), store
    const float gA = gate[((size_t)b * SS + rowA) * HH + h] / lA;
    const float gB = gate[((size_t)b * SS + rowB) * HH + h] / lB;
#pragma unroll
    for (int nt = 0; nt < 16; ++nt) {
        const int col = h * DK + 8 * nt + 2 * ctid;
        float2 vA = make_float2(tf32f(oacc[nt][0] * gA), tf32f(oacc[nt][1] * gA));
        float2 vB = make_float2(tf32f(oacc[nt][2] * gB), tf32f(oacc[nt][3] * gB));
        *(float2*)&o[((size_t)b * SS + rowA) * DD + col] = vA;
        *(float2*)&o[((size_t)b * SS + rowB) * DD + col] = vB;
    }
}

// ==================== launcher ====================
extern "C" void kernel_launch(void* const* d_in, const int* in_sizes, int n_in,
                              void* d_out, int out_size) {
    const float* states     = (const float*)d_in[0];
    const float* head_scale = (const float*)d_in[2];
    const float* Wq = (const float*)d_in[3];
    const float* bq = (const float*)d_in[4];
    const float* Wk = (const float*)d_in[5];
    const float* bk = (const float*)d_in[6];
    const float* Wv = (const float*)d_in[7];
    const float* bv = (const float*)d_in[8];
    const float* Wg = (const float*)d_in[9];
    const float* bg = (const float*)d_in[10];
    const float* Wo = (const float*)d_in[11];
    const float* bo = (const float*)d_in[12];

    float *qb_, *kb_, *vb_, *gb_, *ob_, *xr, *wq, *wk, *wv, *wo;
    cudaGetSymbolAddress((void**)&qb_, g_q);
    cudaGetSymbolAddress((void**)&kb_, g_k);
    cudaGetSymbolAddress((void**)&vb_, g_v);
    cudaGetSymbolAddress((void**)&gb_, g_gate);
    cudaGetSymbolAddress((void**)&ob_, g_o);
    cudaGetSymbolAddress((void**)&xr, g_xr);
    cudaGetSymbolAddress((void**)&wq, g_wq);
    cudaGetSymbolAddress((void**)&wk, g_wk);
    cudaGetSymbolAddress((void**)&wv, g_wv);
    cudaGetSymbolAddress((void**)&wo, g_wo);

    cudaFuncSetAttribute(attn_mma, cudaFuncAttributeMaxDynamicSharedMemorySize,
                         ATTN_SMEM_BYTES);
    cudaFuncSetAttribute(gemm_tf32, cudaFuncAttributeMaxDynamicSharedMemorySize,
                         GEMM_SMEM_BYTES);

    // pre-round inputs to tf32 (RNA); bit-identical to rounding at STS time
    const int nX4 = MM * DD / 4, nW4 = DD * DD / 4;
    round_tf32_kernel<<<(nX4 + 255) / 256, 256>>>(states, xr, nX4);
    round_tf32_kernel<<<(nW4 + 255) / 256, 256>>>(Wq, wq, nW4);
    round_tf32_kernel<<<(nW4 + 255) / 256, 256>>>(Wk, wk, nW4);
    round_tf32_kernel<<<(nW4 + 255) / 256, 256>>>(Wv, wv, nW4);
    round_tf32_kernel<<<(nW4 + 255) / 256, 256>>>(Wo, wo, nW4);

    // fused QKV projection
    dim3 qkv_grid(DD / TBN, MM / TBM, 3);   // (8, 32, 3)
    gemm_tf32<<<qkv_grid, 256, GEMM_SMEM_BYTES>>>(xr,
        wq, bq, qb_, wk, bk, kb_, wv, bv, vb_, 1);

    gate_kernel<<<MM, 128>>>(states, Wg, bg, gb_);

    dim3 attn_grid(SS / AQ, HH, BB);        // (16, 16, 2)
    attn_mma<<<attn_grid, 256, ATTN_SMEM_BYTES>>>(qb_, kb_, vb_, gb_, ob_, head_scale);

    dim3 out_grid(DD / TBN, MM / TBM, 1);   // (8, 32, 1)
    gemm_tf32<<<out_grid, 256, GEMM_SMEM_BYTES>>>(ob_,
        wo, bo, (float*)d_out, wo, bo, (float*)d_out, wo, bo, (float*)d_out, 0);
}